// round 7
// baseline (speedup 1.0000x reference)
#include <cuda_runtime.h>
#include <cuda_fp16.h>
#include <cuda_bf16.h>
#include <mma.h>
#include <stdint.h>

using namespace nvcuda;

#define T_ROWS   256
#define K_DIM    8192
#define M_DIM    8192
#define N_CODES  1024
#define GP_ELEMS 1816   // 227 * 8

// scratch (device globals: allocation-free per harness rules)
__device__ __half  g_gp[2048];               // canonical fp16 codebook
__device__ __half  g_xh[T_ROWS * K_DIM];     // 4 MB
__device__ float   g_z [T_ROWS * M_DIM];     // 8 MB

__device__ __forceinline__ uint32_t smem_u32(const void* p) {
    uint32_t a;
    asm("{ .reg .u64 t; cvta.to.shared.u64 t, %1; cvt.u32.u64 %0, t; }"
        : "=r"(a) : "l"(p));
    return a;
}
__device__ __forceinline__ void cp_async16(uint32_t dst, const void* src) {
    asm volatile("cp.async.cg.shared.global [%0], [%1], 16;" :: "r"(dst), "l"(src));
}

// ---------------------------------------------------------------------------
// K0: normalize grid_part to fp16 regardless of delivered dtype.
// ---------------------------------------------------------------------------
__global__ void prep_gp_kernel(const void* __restrict__ gp_raw)
{
    const uint32_t w0 = *(const uint32_t*)gp_raw;
    const int i = threadIdx.x + blockIdx.x * blockDim.x;
    if (i >= GP_ELEMS) return;
    float v;
    if (w0 == 0x3F000000u)        v = ((const float*)gp_raw)[i];
    else if (w0 == 0x3F003F00u)   v = __bfloat162float(((const __nv_bfloat16*)gp_raw)[i]);
    else                          v = __half2float(((const __half*)gp_raw)[i]);
    g_gp[i] = __float2half(v);
}

// ---------------------------------------------------------------------------
// K1: x = SU*x ; FWHT(8192) ; /(sqrt(8192)*1024) ; fp16   (512 threads)
// ---------------------------------------------------------------------------
__global__ void __launch_bounds__(512) fwht_in_kernel(const float* __restrict__ x,
                                                      const float* __restrict__ SU)
{
    __shared__ float s[K_DIM];
    const int row = blockIdx.x;
    const float* xr = x + (size_t)row * K_DIM;
    for (int i = threadIdx.x; i < K_DIM; i += 512)
        s[i] = xr[i] * SU[i];
    __syncthreads();
    for (int h = 1; h < K_DIM; h <<= 1) {
        #pragma unroll 1
        for (int j = 0; j < 8; j++) {
            int i   = threadIdx.x + j * 512;          // 0..4095
            int idx = ((i & ~(h - 1)) << 1) | (i & (h - 1));
            float a = s[idx], b = s[idx + h];
            s[idx]     = a + b;
            s[idx + h] = a - b;
        }
        __syncthreads();
    }
    const float c = 1.0789593218788508e-05f;   // 1/(sqrt(8192)*1024)
    __half* o = g_xh + (size_t)row * K_DIM;
    for (int i = threadIdx.x; i < K_DIM; i += 512)
        o[i] = __float2half(s[i] * c);
}

// ---------------------------------------------------------------------------
// K3: fused dequant + wmma GEMM, 3-stage cp.async pipeline, 2 blocks/SM
// block: 128(m) x 64(n), K-chunk 64; warps 4m x 2n, warp tile 32x32
// ---------------------------------------------------------------------------
#define STAGES      3
#define NCHUNK      128            // 8192 / 64
#define BMT         128
#define BNT         64
#define LDSM        72             // 64 + 8 pad halves; 144B row stride
#define A_BYTES     (128 * 144)    // 18432
#define B_BYTES     (64 * 144)     // 9216
#define STAGE_BYTES (A_BYTES + B_BYTES)
#define SM_CB       0              // codebook 227*16B
#define SM_LUT      3712           // sign LUT 256*16B
#define SM_STAGE    7808
#define SMEM_GEMM   (SM_STAGE + STAGES * STAGE_BYTES)   // 90752

__global__ void __launch_bounds__(256, 2) gemm_fused_kernel(const int* __restrict__ Q)
{
    extern __shared__ char smem[];
    const uint32_t sb = smem_u32(smem);
    const int tid = threadIdx.x;
    const int warpId = tid >> 5;
    const int warpM  = warpId & 3;        // 0..3 -> 32 m-rows
    const int warpN  = warpId >> 2;       // 0..1 -> 32 n-cols
    const int n0 = blockIdx.x * BNT;
    const int m0 = blockIdx.y * BMT;

    if (tid < 227)
        *(uint4*)(smem + SM_CB + tid * 16) = *(const uint4*)(g_gp + tid * 8);
    {   // sign LUT
        uint32_t f = tid & 255;
        uint4 m;
        m.x = ((f & 1)  ? 0x8000u : 0u) | ((f & 2)   ? 0x80000000u : 0u);
        m.y = ((f & 4)  ? 0x8000u : 0u) | ((f & 8)   ? 0x80000000u : 0u);
        m.z = ((f & 16) ? 0x8000u : 0u) | ((f & 32)  ? 0x80000000u : 0u);
        m.w = ((f & 64) ? 0x8000u : 0u) | ((f & 128) ? 0x80000000u : 0u);
        *(uint4*)(smem + SM_LUT + f * 16) = m;
    }
    __syncthreads();

    // B decode mapping: 512 codes/chunk, 2 per thread
    const int q_row = tid >> 2;           // 0..63
    const int q_j0  = (tid & 3) * 2;      // 0,2,4,6
    const int2* qptr = (const int2*)(Q + (size_t)(n0 + q_row) * N_CODES) + (q_j0 >> 1);

    wmma::fragment<wmma::accumulator, 16, 16, 16, float> acc[2][2];
    #pragma unroll
    for (int i = 0; i < 2; i++)
        #pragma unroll
        for (int j = 0; j < 2; j++)
            wmma::fill_fragment(acc[i][j], 0.0f);

    auto fill = [&](int c, int2 q) {
        const int s = c % STAGES;
        const uint32_t abase = sb + SM_STAGE + s * STAGE_BYTES;
        // A tile: 128 rows x 128B
        #pragma unroll
        for (int u = 0; u < 4; u++) {
            int lin = tid + u * 256;            // 0..1023 16B units
            int row = lin >> 3, c16 = lin & 7;
            cp_async16(abase + row * 144 + c16 * 16,
                       g_xh + (size_t)(m0 + row) * K_DIM + c * 64 + c16 * 8);
        }
        // B tile: decode 2 codes
        char* bb = smem + SM_STAGE + s * STAGE_BYTES + A_BYTES;
        const int qs[2] = {q.x, q.y};
        #pragma unroll
        for (int e = 0; e < 2; e++) {
            int idx = qs[e] + 32768;
            const uint4 cb = *(const uint4*)(smem + SM_CB  + (idx & 255) * 16);
            const uint4 sm = *(const uint4*)(smem + SM_LUT + (idx >> 8)  * 16);
            uint4 o;
            o.x = cb.x ^ sm.x;  o.y = cb.y ^ sm.y;
            o.z = cb.z ^ sm.z;  o.w = cb.w ^ sm.w;
            *(uint4*)(bb + q_row * 144 + (q_j0 + e) * 16) = o;
        }
    };

    fill(0, qptr[0]);
    asm volatile("cp.async.commit_group;" ::: "memory");
    fill(1, qptr[4]);
    asm volatile("cp.async.commit_group;" ::: "memory");

    for (int i = 0; i < NCHUNK; i++) {
        int2 qn = {0, 0};
        if (i + 2 < NCHUNK) qn = qptr[(i + 2) * 4];

        asm volatile("cp.async.wait_group 1;" ::: "memory");
        __syncthreads();

        const int s = i % STAGES;
        const __half* As = (const __half*)(smem + SM_STAGE + s * STAGE_BYTES);
        const __half* Bs = (const __half*)(smem + SM_STAGE + s * STAGE_BYTES + A_BYTES);
        #pragma unroll
        for (int kk = 0; kk < 4; kk++) {
            wmma::fragment<wmma::matrix_a, 16, 16, 16, __half, wmma::row_major> a[2];
            wmma::fragment<wmma::matrix_b, 16, 16, 16, __half, wmma::col_major> b[2];
            #pragma unroll
            for (int ii = 0; ii < 2; ii++)
                wmma::load_matrix_sync(a[ii], &As[(warpM * 32 + ii * 16) * LDSM + kk * 16], LDSM);
            #pragma unroll
            for (int jj = 0; jj < 2; jj++)
                wmma::load_matrix_sync(b[jj], &Bs[(warpN * 32 + jj * 16) * LDSM + kk * 16], LDSM);
            #pragma unroll
            for (int ii = 0; ii < 2; ii++)
                #pragma unroll
                for (int jj = 0; jj < 2; jj++)
                    wmma::mma_sync(acc[ii][jj], a[ii], b[jj], acc[ii][jj]);
        }
        __syncthreads();

        if (i + 2 < NCHUNK) fill(i + 2, qn);
        asm volatile("cp.async.commit_group;" ::: "memory");
    }

    #pragma unroll
    for (int ii = 0; ii < 2; ii++)
        #pragma unroll
        for (int jj = 0; jj < 2; jj++)
            wmma::store_matrix_sync(
                &g_z[(size_t)(m0 + warpM * 32 + ii * 16) * M_DIM +
                     n0 + warpN * 32 + jj * 16],
                acc[ii][jj], M_DIM, wmma::mem_row_major);
}

// ---------------------------------------------------------------------------
// K4: out = SV * fwht(z) * (Wscale*1024/sqrt(8192))   (512 threads)
// ---------------------------------------------------------------------------
__global__ void __launch_bounds__(512) fwht_out_kernel(const float* __restrict__ SV,
                                                       const float* __restrict__ Wscale,
                                                       float* __restrict__ out)
{
    __shared__ float s[M_DIM];
    const int row = blockIdx.x;
    const float* zr = g_z + (size_t)row * M_DIM;
    for (int i = threadIdx.x; i < M_DIM; i += 512)
        s[i] = zr[i];
    __syncthreads();
    for (int h = 1; h < M_DIM; h <<= 1) {
        #pragma unroll 1
        for (int j = 0; j < 8; j++) {
            int i   = threadIdx.x + j * 512;
            int idx = ((i & ~(h - 1)) << 1) | (i & (h - 1));
            float a = s[idx], b = s[idx + h];
            s[idx]     = a + b;
            s[idx + h] = a - b;
        }
        __syncthreads();
    }
    const float c = Wscale[0] * 11.313708498984761f;  // 1024/sqrt(8192)
    float* o = out + (size_t)row * M_DIM;
    for (int i = threadIdx.x; i < M_DIM; i += 512)
        o[i] = s[i] * c * SV[i];
}

// ---------------------------------------------------------------------------
extern "C" void kernel_launch(void* const* d_in, const int* in_sizes, int n_in,
                              void* d_out, int out_size)
{
    const float* x  = nullptr;  const int*   Q  = nullptr;
    const float* SU = nullptr;  const float* SV = nullptr;
    const float* Ws = nullptr;  const void*  gp = nullptr;
    for (int i = 0; i < n_in; i++) {
        int s = in_sizes[i];
        if      (s == T_ROWS * K_DIM)   x  = (const float*)d_in[i];
        else if (s == M_DIM * N_CODES)  Q  = (const int*)d_in[i];
        else if (s == 1)                Ws = (const float*)d_in[i];
        else if (s == K_DIM) { if (!SU) SU = (const float*)d_in[i];
                               else     SV = (const float*)d_in[i]; }
        else                            gp = d_in[i];
    }
    float* out = (float*)d_out;

    static bool smem_set = false;
    if (!smem_set) {
        cudaFuncSetAttribute(gemm_fused_kernel,
                             cudaFuncAttributeMaxDynamicSharedMemorySize, SMEM_GEMM);
        smem_set = true;
    }

    prep_gp_kernel<<<8, 256>>>(gp);
    fwht_in_kernel<<<T_ROWS, 512>>>(x, SU);
    dim3 grid(M_DIM / BNT, T_ROWS / BMT);
    gemm_fused_kernel<<<grid, 256, SMEM_GEMM>>>(Q);
    fwht_out_kernel<<<T_ROWS, 512>>>(SV, Ws, out);
}